// round 1
// baseline (speedup 1.0000x reference)
#include <cuda_runtime.h>
#include <math.h>

#define NN 50000
#define EE 800000
#define DD 256
#define HH 8
#define ND (NN * DD)
#define EH (EE * HH)
#define LAMBDA_INIT 0.6321205588285577f

// ---------------- scratch (static device globals; no allocation) ----------------
__device__ float    g_V[ND];          // V = x @ v_w^T          51.2 MB
__device__ float    g_scores[EE*16];  // raw scores -> exp vals 51.2 MB
__device__ unsigned g_max1[NN*HH];
__device__ unsigned g_max2[NN*HH];
__device__ float    g_sum1[NN*HH];
__device__ float    g_sum2[NN*HH];
__device__ float    g_acc[ND];        // scatter accumulator    51.2 MB
__device__ float    g_beta;
__device__ int      g_is64;

// ---------------- helpers ----------------
__device__ __forceinline__ unsigned fenc(float f) {
    unsigned u = __float_as_uint(f);
    return (u & 0x80000000u) ? ~u : (u | 0x80000000u);
}
__device__ __forceinline__ float fdec(unsigned u) {
    return (u & 0x80000000u) ? __uint_as_float(u ^ 0x80000000u) : __uint_as_float(~u);
}
__device__ __forceinline__ int ldidx(const void* p, long long i, int is64) {
    return is64 ? (int)((const long long*)p)[i] : ((const int*)p)[i];
}
__device__ __forceinline__ void red_add_v4(float* addr, float4 v) {
    asm volatile("red.global.add.v4.f32 [%0], {%1,%2,%3,%4};"
                 :: "l"(addr), "f"(v.x), "f"(v.y), "f"(v.z), "f"(v.w) : "memory");
}

// ---------------- dtype sniff for edge_index (int32 vs int64) ----------------
// Values are < 50000, so if the buffer holds int64, every odd int32 word is 0.
__global__ void k_detect(const void* ei) {
    const int* p = (const int*)ei;
    int all0 = 1;
    for (int i = 0; i < 256; i++) {
        if (p[2*i + 1] != 0) { all0 = 0; break; }
    }
    g_is64 = all0;
}

// ---------------- zero init (every launch; graph replays) ----------------
__global__ void k_init() {
    long long stride = (long long)gridDim.x * blockDim.x;
    for (long long i = blockIdx.x * (long long)blockDim.x + threadIdx.x; i < ND; i += stride)
        g_acc[i] = 0.0f;
    for (long long i = blockIdx.x * (long long)blockDim.x + threadIdx.x; i < NN*HH; i += stride) {
        g_max1[i] = 0u;
        g_max2[i] = 0u;
        g_sum1[i] = 0.0f;
        g_sum2[i] = 0.0f;
    }
}

// ---------------- beta ----------------
__global__ void k_beta(const float* __restrict__ lq, const float* __restrict__ lk,
                       float* out_beta) {
    __shared__ float red[128];
    int t = threadIdx.x;
    float p = (t < 100) ? lq[t] * lk[t] : 0.0f;
    red[t] = p;
    __syncthreads();
    for (int s = 64; s > 0; s >>= 1) {
        if (t < s) red[t] += red[t + s];
        __syncthreads();
    }
    if (t == 0) {
        float lam1 = expf(red[0]);
        float b = 1.0f / (1.0f + expf(-lam1 * LAMBDA_INIT));
        g_beta = b;
        if (out_beta) *out_beta = b;
    }
}

// ---------------- fp32 SGEMM: C[M,256] = A[M,256] @ B[256,256]^T ----------------
#define BM 64
#define BN 64
#define BK 16
__global__ void k_gemm_abt(const float* __restrict__ A, const float* __restrict__ B,
                           float* __restrict__ C, int M) {
    __shared__ float As[BK][BM + 1];
    __shared__ float Bs[BK][BN + 1];
    int bm = blockIdx.y * BM, bn = blockIdx.x * BN;
    int tid = threadIdx.x;                   // 256 threads
    int tr = tid >> 4, tc = tid & 15;        // 16x16 thread tile
    int lrow = tid >> 2;                     // loader row 0..63
    int lcol = (tid & 3) << 2;               // loader col {0,4,8,12}

    float acc[4][4] = {};
    for (int k0 = 0; k0 < 256; k0 += BK) {
        // A tile (rows may exceed M on last block)
        float4 av = make_float4(0.f, 0.f, 0.f, 0.f);
        int gr = bm + lrow;
        if (gr < M) av = *(const float4*)&A[(long long)gr * DD + k0 + lcol];
        As[lcol + 0][lrow] = av.x; As[lcol + 1][lrow] = av.y;
        As[lcol + 2][lrow] = av.z; As[lcol + 3][lrow] = av.w;
        // B tile: Bs[k][n] = B[(bn+n)*256 + k0+k]  (B always 256x256)
        float4 bv = *(const float4*)&B[(long long)(bn + lrow) * DD + k0 + lcol];
        Bs[lcol + 0][lrow] = bv.x; Bs[lcol + 1][lrow] = bv.y;
        Bs[lcol + 2][lrow] = bv.z; Bs[lcol + 3][lrow] = bv.w;
        __syncthreads();
        #pragma unroll
        for (int k = 0; k < BK; k++) {
            float a[4], b[4];
            #pragma unroll
            for (int i = 0; i < 4; i++) a[i] = As[k][tr * 4 + i];
            #pragma unroll
            for (int j = 0; j < 4; j++) b[j] = Bs[k][tc * 4 + j];
            #pragma unroll
            for (int i = 0; i < 4; i++)
                #pragma unroll
                for (int j = 0; j < 4; j++)
                    acc[i][j] = fmaf(a[i], b[j], acc[i][j]);
        }
        __syncthreads();
    }
    #pragma unroll
    for (int i = 0; i < 4; i++) {
        int r = bm + tr * 4 + i;
        if (r < M) {
            #pragma unroll
            for (int j = 0; j < 4; j++)
                C[(long long)r * DD + bn + tc * 4 + j] = acc[i][j];
        }
    }
}

// ---------------- edge MLP: scores + segment max ----------------
// h = gelu(ea @ w1^T + b1)  (6 -> 256), scores = h @ w2^T + b2  (256 -> 16)
__global__ void k_edge_mlp(const float* __restrict__ ea_g,
                           const float* __restrict__ w1, const float* __restrict__ b1,
                           const float* __restrict__ w2, const float* __restrict__ b2,
                           const void* __restrict__ ei) {
    __shared__ float w1p[256 * 8];   // [w1 row (6), b1, pad]
    __shared__ float w2s[256 * 16];  // w2s[j*16+t] = w2[t*256+j]
    __shared__ float b2s[16];

    int tid = threadIdx.x;           // 256 threads
    for (int idx = tid; idx < 256 * 8; idx += 256) {
        int j = idx >> 3, c = idx & 7;
        float v = 0.0f;
        if (c < 6)       v = w1[j * 6 + c];
        else if (c == 6) v = b1[j];
        w1p[idx] = v;
    }
    for (int idx = tid; idx < 256 * 16; idx += 256) {
        int j = idx >> 4, t = idx & 15;
        w2s[idx] = w2[t * 256 + j];
    }
    if (tid < 16) b2s[tid] = b2[tid];
    __syncthreads();

    int e = blockIdx.x * 256 + tid;
    if (e >= EE) return;
    int is64 = g_is64;

    float ea[6];
    #pragma unroll
    for (int k = 0; k < 6; k++) ea[k] = ea_g[(long long)e * 6 + k];

    float acc[16];
    #pragma unroll
    for (int t = 0; t < 16; t++) acc[t] = b2s[t];

    const float4* w1p4 = (const float4*)w1p;
    const float4* w2s4 = (const float4*)w2s;
    #pragma unroll 4
    for (int j = 0; j < 256; j++) {
        float4 p0 = w1p4[j * 2 + 0];
        float4 p1 = w1p4[j * 2 + 1];
        float s = p1.z;  // b1[j]
        s = fmaf(ea[0], p0.x, s); s = fmaf(ea[1], p0.y, s);
        s = fmaf(ea[2], p0.z, s); s = fmaf(ea[3], p0.w, s);
        s = fmaf(ea[4], p1.x, s); s = fmaf(ea[5], p1.y, s);
        float h = s * normcdff(s);  // exact GELU
        float4 q0 = w2s4[j * 4 + 0], q1 = w2s4[j * 4 + 1];
        float4 q2 = w2s4[j * 4 + 2], q3 = w2s4[j * 4 + 3];
        acc[0]  = fmaf(h, q0.x, acc[0]);  acc[1]  = fmaf(h, q0.y, acc[1]);
        acc[2]  = fmaf(h, q0.z, acc[2]);  acc[3]  = fmaf(h, q0.w, acc[3]);
        acc[4]  = fmaf(h, q1.x, acc[4]);  acc[5]  = fmaf(h, q1.y, acc[5]);
        acc[6]  = fmaf(h, q1.z, acc[6]);  acc[7]  = fmaf(h, q1.w, acc[7]);
        acc[8]  = fmaf(h, q2.x, acc[8]);  acc[9]  = fmaf(h, q2.y, acc[9]);
        acc[10] = fmaf(h, q2.z, acc[10]); acc[11] = fmaf(h, q2.w, acc[11]);
        acc[12] = fmaf(h, q3.x, acc[12]); acc[13] = fmaf(h, q3.y, acc[13]);
        acc[14] = fmaf(h, q3.z, acc[14]); acc[15] = fmaf(h, q3.w, acc[15]);
    }

    int tgt = ldidx(ei, (long long)EE + e, is64);
    #pragma unroll
    for (int t = 0; t < 16; t++) g_scores[(long long)e * 16 + t] = acc[t];
    #pragma unroll
    for (int h = 0; h < HH; h++) {
        atomicMax(&g_max1[tgt * HH + h], fenc(acc[2 * h]));
        atomicMax(&g_max2[tgt * HH + h], fenc(acc[2 * h + 1]));
    }
}

// ---------------- exp + segment sum ----------------
__global__ void k_exp(const void* __restrict__ ei) {
    long long tid = (long long)blockIdx.x * blockDim.x + threadIdx.x;
    if (tid >= (long long)EE * HH) return;
    int e = (int)(tid >> 3);
    int h = (int)(tid & 7);
    int is64 = g_is64;
    int tgt = ldidx(ei, (long long)EE + e, is64);

    float s1 = g_scores[(long long)e * 16 + 2 * h];
    float s2 = g_scores[(long long)e * 16 + 2 * h + 1];
    float m1 = fdec(g_max1[tgt * HH + h]);
    float m2 = fdec(g_max2[tgt * HH + h]);
    float e1 = expf(s1 - m1);
    float e2 = expf(s2 - m2);
    g_scores[(long long)e * 16 + 2 * h]     = e1;
    g_scores[(long long)e * 16 + 2 * h + 1] = e2;
    atomicAdd(&g_sum1[tgt * HH + h], e1);
    atomicAdd(&g_sum2[tgt * HH + h], e2);
}

// ---------------- finalize attn + gather V[src] + scatter-add ----------------
// one warp per edge; lane l covers output floats [8l, 8l+8) -> head = l/4
__global__ void k_scatter(const void* __restrict__ ei, float* __restrict__ attn_out) {
    int gw = (blockIdx.x * blockDim.x + threadIdx.x) >> 5;
    if (gw >= EE) return;
    int lane = threadIdx.x & 31;
    int e = gw;
    int is64 = g_is64;
    int src = ldidx(ei, e, is64);
    int tgt = ldidx(ei, (long long)EE + e, is64);

    int h = lane >> 2;
    float e1 = g_scores[(long long)e * 16 + 2 * h];
    float e2 = g_scores[(long long)e * 16 + 2 * h + 1];
    float s1 = g_sum1[tgt * HH + h];
    float s2 = g_sum2[tgt * HH + h];
    float beta = g_beta;
    float attn = e1 / s1 - beta * (e2 / s2);

    if (attn_out && (lane & 3) == 0)
        attn_out[(long long)e * HH + h] = attn;

    const float4* v = (const float4*)&g_V[(long long)src * DD + lane * 8];
    float4 a = v[0], b = v[1];
    a.x *= attn; a.y *= attn; a.z *= attn; a.w *= attn;
    b.x *= attn; b.y *= attn; b.z *= attn; b.w *= attn;
    float* dst = &g_acc[(long long)tgt * DD + lane * 8];
    red_add_v4(dst, a);
    red_add_v4(dst + 4, b);
}

// ---------------- launch ----------------
extern "C" void kernel_launch(void* const* d_in, const int* in_sizes, int n_in,
                              void* d_out, int out_size) {
    const float* x    = (const float*)d_in[0];
    const float* eatt = (const float*)d_in[1];
    const float* v_w  = (const float*)d_in[2];
    const float* o_w  = (const float*)d_in[3];
    const float* e_w1 = (const float*)d_in[4];
    const float* e_b1 = (const float*)d_in[5];
    const float* e_w2 = (const float*)d_in[6];
    const float* e_b2 = (const float*)d_in[7];
    const float* lq   = (const float*)d_in[8];
    const float* lk   = (const float*)d_in[9];
    const void*  ei   = d_in[10];

    float* out = (float*)d_out;
    float* attn_out = (out_size >= ND + EH)     ? out + ND      : nullptr;
    float* beta_out = (out_size >= ND + EH + 1) ? out + ND + EH : nullptr;

    float* gV, *gAcc;
    cudaGetSymbolAddress((void**)&gV, g_V);
    cudaGetSymbolAddress((void**)&gAcc, g_acc);

    k_detect<<<1, 1>>>(ei);
    k_init<<<2048, 256>>>();
    k_beta<<<1, 128>>>(lq, lk, beta_out);

    dim3 ggrid(DD / BN, (NN + BM - 1) / BM);
    k_gemm_abt<<<ggrid, 256>>>(x, v_w, gV, NN);

    k_edge_mlp<<<EE / 256, 256>>>(eatt, e_w1, e_b1, e_w2, e_b2, ei);
    k_exp<<<(EE * HH + 255) / 256, 256>>>(ei);
    k_scatter<<<EE * 32 / 256, 256>>>(ei, attn_out);

    k_gemm_abt<<<ggrid, 256>>>(gAcc, o_w, out, NN);
}

// round 2
// speedup vs baseline: 1.9253x; 1.9253x over previous
#include <cuda_runtime.h>
#include <math.h>

#define NN 50000
#define EE 800000
#define DD 256
#define HH 8
#define ND (NN * DD)
#define EH (EE * HH)
#define LAMBDA_INIT 0.6321205588285577f

// ---------------- scratch (static device globals; no allocation) ----------------
__device__ float g_V[ND];          // V = x @ v_w^T          51.2 MB
__device__ float g_exp[EE * 16];   // exp(scores)            51.2 MB
__device__ float g_sums[NN * 16];  // [node][2h+j] segment sums
__device__ float g_acc[ND];        // scatter accumulator    51.2 MB
__device__ float g_beta;
__device__ int   g_is64;

// ---------------- helpers ----------------
__device__ __forceinline__ int ldidx(const void* p, long long i, int is64) {
    return is64 ? (int)((const long long*)p)[i] : ((const int*)p)[i];
}
__device__ __forceinline__ void red_add_v4(float* addr, float4 v) {
    asm volatile("red.global.add.v4.f32 [%0], {%1,%2,%3,%4};"
                 :: "l"(addr), "f"(v.x), "f"(v.y), "f"(v.z), "f"(v.w) : "memory");
}

// ---------------- dtype sniff for edge_index (int32 vs int64) ----------------
__global__ void k_detect(const void* ei) {
    const int* p = (const int*)ei;
    int all0 = 1;
    for (int i = 0; i < 256; i++) {
        if (p[2 * i + 1] != 0) { all0 = 0; break; }
    }
    g_is64 = all0;
}

// ---------------- zero init (every launch; graph replays) ----------------
__global__ void k_init() {
    long long stride = (long long)gridDim.x * blockDim.x;
    for (long long i = blockIdx.x * (long long)blockDim.x + threadIdx.x; i < ND; i += stride)
        g_acc[i] = 0.0f;
    for (long long i = blockIdx.x * (long long)blockDim.x + threadIdx.x; i < NN * 16; i += stride)
        g_sums[i] = 0.0f;
}

// ---------------- beta ----------------
__global__ void k_beta(const float* __restrict__ lq, const float* __restrict__ lk,
                       float* out_beta) {
    __shared__ float red[128];
    int t = threadIdx.x;
    float p = (t < 100) ? lq[t] * lk[t] : 0.0f;
    red[t] = p;
    __syncthreads();
    for (int s = 64; s > 0; s >>= 1) {
        if (t < s) red[t] += red[t + s];
        __syncthreads();
    }
    if (t == 0) {
        float lam1 = expf(red[0]);
        float b = 1.0f / (1.0f + expf(-lam1 * LAMBDA_INIT));
        g_beta = b;
        if (out_beta) *out_beta = b;
    }
}

// ---------------- fp32 SGEMM: C[M,256] = A[M,256] @ B[256,256]^T ----------------
// 128x128 block tile, BK=8, 8x8 micro-tile per thread (split 4+4 with 64 offset)
__global__ void __launch_bounds__(256, 2)
k_gemm_abt(const float* __restrict__ A, const float* __restrict__ B,
           float* __restrict__ C, int M) {
    __shared__ float As[8][128 + 4];
    __shared__ float Bs[8][128 + 4];
    int bm = blockIdx.y * 128, bn = blockIdx.x * 128;
    int tid = threadIdx.x;        // 256 threads
    int lrow = tid >> 1;          // 0..127
    int lk = (tid & 1) * 4;       // 0 or 4
    int tr = tid >> 4;            // 0..15
    int tc = tid & 15;            // 0..15

    float acc[8][8] = {};
    for (int k0 = 0; k0 < 256; k0 += 8) {
        float4 av = make_float4(0.f, 0.f, 0.f, 0.f);
        int ar = bm + lrow;
        if (ar < M) av = *(const float4*)&A[(size_t)ar * DD + k0 + lk];
        As[lk + 0][lrow] = av.x; As[lk + 1][lrow] = av.y;
        As[lk + 2][lrow] = av.z; As[lk + 3][lrow] = av.w;
        float4 bv = *(const float4*)&B[(size_t)(bn + lrow) * DD + k0 + lk];
        Bs[lk + 0][lrow] = bv.x; Bs[lk + 1][lrow] = bv.y;
        Bs[lk + 2][lrow] = bv.z; Bs[lk + 3][lrow] = bv.w;
        __syncthreads();
        #pragma unroll
        for (int k = 0; k < 8; k++) {
            float4 a0 = *(const float4*)&As[k][tr * 4];
            float4 a1 = *(const float4*)&As[k][64 + tr * 4];
            float4 b0 = *(const float4*)&Bs[k][tc * 4];
            float4 b1 = *(const float4*)&Bs[k][64 + tc * 4];
            float a[8] = {a0.x, a0.y, a0.z, a0.w, a1.x, a1.y, a1.z, a1.w};
            float b[8] = {b0.x, b0.y, b0.z, b0.w, b1.x, b1.y, b1.z, b1.w};
            #pragma unroll
            for (int i = 0; i < 8; i++)
                #pragma unroll
                for (int j = 0; j < 8; j++)
                    acc[i][j] = fmaf(a[i], b[j], acc[i][j]);
        }
        __syncthreads();
    }
    #pragma unroll
    for (int i = 0; i < 8; i++) {
        int r = bm + ((i < 4) ? (tr * 4 + i) : (64 + tr * 4 + i - 4));
        if (r < M) {
            float4 v0 = make_float4(acc[i][0], acc[i][1], acc[i][2], acc[i][3]);
            float4 v1 = make_float4(acc[i][4], acc[i][5], acc[i][6], acc[i][7]);
            *(float4*)&C[(size_t)r * DD + bn + tc * 4] = v0;
            *(float4*)&C[(size_t)r * DD + bn + 64 + tc * 4] = v1;
        }
    }
}

// ---------------- edge MLP: fused scores -> exp -> segment sum ----------------
// h = gelu(ea @ w1^T + b1)  (6 -> 256), scores = h @ w2^T + b2  (256 -> 16)
// No max-subtraction: |scores| << 88 by construction, exp is fp32-safe and the
// softmax ratio e/sum(e) is analytically identical to the max-subtracted form.
__global__ void k_edge_mlp(const float* __restrict__ ea_g,
                           const float* __restrict__ w1, const float* __restrict__ b1,
                           const float* __restrict__ w2, const float* __restrict__ b2,
                           const void* __restrict__ ei) {
    __shared__ float w1p[256 * 8];   // [w1 row (6), b1, pad]
    __shared__ float w2s[256 * 16];  // w2s[j*16+t] = w2[t*256+j]
    __shared__ float b2s[16];

    int tid = threadIdx.x;           // 256 threads
    for (int idx = tid; idx < 256 * 8; idx += 256) {
        int j = idx >> 3, c = idx & 7;
        float v = 0.0f;
        if (c < 6)       v = w1[j * 6 + c];
        else if (c == 6) v = b1[j];
        w1p[idx] = v;
    }
    for (int idx = tid; idx < 256 * 16; idx += 256) {
        int j = idx >> 4, t = idx & 15;
        w2s[idx] = w2[t * 256 + j];
    }
    if (tid < 16) b2s[tid] = b2[tid];
    __syncthreads();

    int e = blockIdx.x * 256 + tid;
    if (e >= EE) return;
    int is64 = g_is64;

    float ea[6];
    #pragma unroll
    for (int k = 0; k < 6; k++) ea[k] = ea_g[(long long)e * 6 + k];

    float acc[16];
    #pragma unroll
    for (int t = 0; t < 16; t++) acc[t] = b2s[t];

    const float4* w1p4 = (const float4*)w1p;
    const float4* w2s4 = (const float4*)w2s;
    #pragma unroll 4
    for (int j = 0; j < 256; j++) {
        float4 p0 = w1p4[j * 2 + 0];
        float4 p1 = w1p4[j * 2 + 1];
        float s = p1.z;  // b1[j]
        s = fmaf(ea[0], p0.x, s); s = fmaf(ea[1], p0.y, s);
        s = fmaf(ea[2], p0.z, s); s = fmaf(ea[3], p0.w, s);
        s = fmaf(ea[4], p1.x, s); s = fmaf(ea[5], p1.y, s);
        float h = s * normcdff(s);  // exact GELU
        float4 q0 = w2s4[j * 4 + 0], q1 = w2s4[j * 4 + 1];
        float4 q2 = w2s4[j * 4 + 2], q3 = w2s4[j * 4 + 3];
        acc[0]  = fmaf(h, q0.x, acc[0]);  acc[1]  = fmaf(h, q0.y, acc[1]);
        acc[2]  = fmaf(h, q0.z, acc[2]);  acc[3]  = fmaf(h, q0.w, acc[3]);
        acc[4]  = fmaf(h, q1.x, acc[4]);  acc[5]  = fmaf(h, q1.y, acc[5]);
        acc[6]  = fmaf(h, q1.z, acc[6]);  acc[7]  = fmaf(h, q1.w, acc[7]);
        acc[8]  = fmaf(h, q2.x, acc[8]);  acc[9]  = fmaf(h, q2.y, acc[9]);
        acc[10] = fmaf(h, q2.z, acc[10]); acc[11] = fmaf(h, q2.w, acc[11]);
        acc[12] = fmaf(h, q3.x, acc[12]); acc[13] = fmaf(h, q3.y, acc[13]);
        acc[14] = fmaf(h, q3.z, acc[14]); acc[15] = fmaf(h, q3.w, acc[15]);
    }

    // exp + store + segment-sum (vector reduction atomics)
    float ex[16];
    #pragma unroll
    for (int t = 0; t < 16; t++) ex[t] = __expf(acc[t]);

    float4* sc = (float4*)&g_exp[(long long)e * 16];
    sc[0] = make_float4(ex[0],  ex[1],  ex[2],  ex[3]);
    sc[1] = make_float4(ex[4],  ex[5],  ex[6],  ex[7]);
    sc[2] = make_float4(ex[8],  ex[9],  ex[10], ex[11]);
    sc[3] = make_float4(ex[12], ex[13], ex[14], ex[15]);

    int tgt = ldidx(ei, (long long)EE + e, is64);
    float* sbase = &g_sums[tgt * 16];
    red_add_v4(sbase + 0,  make_float4(ex[0],  ex[1],  ex[2],  ex[3]));
    red_add_v4(sbase + 4,  make_float4(ex[4],  ex[5],  ex[6],  ex[7]));
    red_add_v4(sbase + 8,  make_float4(ex[8],  ex[9],  ex[10], ex[11]));
    red_add_v4(sbase + 12, make_float4(ex[12], ex[13], ex[14], ex[15]));
}

// ---------------- finalize attn + gather V[src] + scatter-add ----------------
// one warp per edge; lane l covers output floats [8l, 8l+8) -> head = l/4
__global__ void k_scatter(const void* __restrict__ ei, float* __restrict__ attn_out) {
    int gw = (blockIdx.x * blockDim.x + threadIdx.x) >> 5;
    if (gw >= EE) return;
    int lane = threadIdx.x & 31;
    int e = gw;
    int is64 = g_is64;
    int src = ldidx(ei, e, is64);
    int tgt = ldidx(ei, (long long)EE + e, is64);

    int h = lane >> 2;
    float e1 = g_exp[(long long)e * 16 + 2 * h];
    float e2 = g_exp[(long long)e * 16 + 2 * h + 1];
    float s1 = g_sums[tgt * 16 + 2 * h];
    float s2 = g_sums[tgt * 16 + 2 * h + 1];
    float beta = g_beta;
    float attn = e1 / s1 - beta * (e2 / s2);

    if (attn_out && (lane & 3) == 0)
        attn_out[(long long)e * HH + h] = attn;

    const float4* v = (const float4*)&g_V[(long long)src * DD + lane * 8];
    float4 a = v[0], b = v[1];
    a.x *= attn; a.y *= attn; a.z *= attn; a.w *= attn;
    b.x *= attn; b.y *= attn; b.z *= attn; b.w *= attn;
    float* dst = &g_acc[(long long)tgt * DD + lane * 8];
    red_add_v4(dst, a);
    red_add_v4(dst + 4, b);
}

// ---------------- launch ----------------
extern "C" void kernel_launch(void* const* d_in, const int* in_sizes, int n_in,
                              void* d_out, int out_size) {
    const float* x    = (const float*)d_in[0];
    const float* eatt = (const float*)d_in[1];
    const float* v_w  = (const float*)d_in[2];
    const float* o_w  = (const float*)d_in[3];
    const float* e_w1 = (const float*)d_in[4];
    const float* e_b1 = (const float*)d_in[5];
    const float* e_w2 = (const float*)d_in[6];
    const float* e_b2 = (const float*)d_in[7];
    const float* lq   = (const float*)d_in[8];
    const float* lk   = (const float*)d_in[9];
    const void*  ei   = d_in[10];

    float* out = (float*)d_out;
    float* attn_out = (out_size >= ND + EH)     ? out + ND      : nullptr;
    float* beta_out = (out_size >= ND + EH + 1) ? out + ND + EH : nullptr;

    float* gV, *gAcc;
    cudaGetSymbolAddress((void**)&gV, g_V);
    cudaGetSymbolAddress((void**)&gAcc, g_acc);

    k_detect<<<1, 1>>>(ei);
    k_init<<<2048, 256>>>();
    k_beta<<<1, 128>>>(lq, lk, beta_out);

    dim3 ggrid(DD / 128, (NN + 127) / 128);
    k_gemm_abt<<<ggrid, 256>>>(x, v_w, gV, NN);

    k_edge_mlp<<<EE / 256, 256>>>(eatt, e_w1, e_b1, e_w2, e_b2, ei);
    k_scatter<<<EE * 32 / 256, 256>>>(ei, attn_out);

    k_gemm_abt<<<ggrid, 256>>>(gAcc, o_w, out, NN);
}

// round 4
// speedup vs baseline: 2.0591x; 1.0695x over previous
#include <cuda_runtime.h>
#include <cuda_fp16.h>
#include <math.h>

#define NN 50000
#define EE 800000
#define DD 256
#define HH 8
#define ND (NN * DD)
#define EH (EE * HH)
#define LAMBDA_INIT 0.6321205588285577f

// ---------------- scratch (static device globals; no allocation) ----------------
__device__ __half g_Vh[ND];        // V = x @ v_w^T (fp16)   25.6 MB
__device__ float  g_exp[EE * 16];  // exp(scores)            51.2 MB
__device__ float  g_sums[NN * 16]; // [node][2h+j] segment sums
__device__ float  g_acc[ND];       // scatter accumulator    51.2 MB
__device__ float  g_beta;
__device__ int    g_is64;

// ---------------- helpers ----------------
__device__ __forceinline__ int ldidx(const void* p, long long i, int is64) {
    return is64 ? (int)((const long long*)p)[i] : ((const int*)p)[i];
}
__device__ __forceinline__ void red_add_v4(float* addr, float4 v) {
    asm volatile("red.global.add.v4.f32 [%0], {%1,%2,%3,%4};"
                 :: "l"(addr), "f"(v.x), "f"(v.y), "f"(v.z), "f"(v.w) : "memory");
}

// exact-enough GELU: s * Phi(s), Phi via Abramowitz-Stegun 7.1.26 erf (abs err 1.5e-7)
__device__ __forceinline__ float gelu_f(float s) {
    float x  = s * 0.70710678118654752f;
    float ax = fabsf(x);
    float t  = __fdividef(1.0f, fmaf(0.3275911f, ax, 1.0f));
    float p  = fmaf(1.061405429f, t, -1.453152027f);
    p = fmaf(p, t, 1.421413741f);
    p = fmaf(p, t, -0.284496736f);
    p = fmaf(p, t, 0.254829592f);
    p *= t;
    float e = __expf(-x * x);
    float erfax = fmaf(-p, e, 1.0f);
    float erfx  = copysignf(erfax, x);
    return s * 0.5f * (1.0f + erfx);
}

// ---------------- dtype sniff for edge_index (int32 vs int64) ----------------
__global__ void k_detect(const void* ei) {
    const int* p = (const int*)ei;
    int nz = (p[2 * threadIdx.x + 1] != 0);
    int any = __syncthreads_or(nz);
    if (threadIdx.x == 0) g_is64 = !any;
}

// ---------------- zero init (every launch; graph replays) ----------------
__global__ void k_init() {
    long long stride = (long long)gridDim.x * blockDim.x;
    for (long long i = blockIdx.x * (long long)blockDim.x + threadIdx.x; i < ND; i += stride)
        g_acc[i] = 0.0f;
    for (long long i = blockIdx.x * (long long)blockDim.x + threadIdx.x; i < NN * 16; i += stride)
        g_sums[i] = 0.0f;
}

// ---------------- beta ----------------
__global__ void k_beta(const float* __restrict__ lq, const float* __restrict__ lk,
                       float* out_beta) {
    __shared__ float red[128];
    int t = threadIdx.x;
    float p = (t < 100) ? lq[t] * lk[t] : 0.0f;
    red[t] = p;
    __syncthreads();
    for (int s = 64; s > 0; s >>= 1) {
        if (t < s) red[t] += red[t + s];
        __syncthreads();
    }
    if (t == 0) {
        float lam1 = expf(red[0]);
        float b = 1.0f / (1.0f + expf(-lam1 * LAMBDA_INIT));
        g_beta = b;
        if (out_beta) *out_beta = b;
    }
}

// ---------------- fp32 SGEMM: C[M,256] = A[M,256] @ B[256,256]^T ----------------
// 128x128 tile, BK=8, double-buffered smem, one sync per K-tile.
// If Ch != nullptr, writes fp16 to Ch instead of fp32 to C.
__global__ void __launch_bounds__(256, 2)
k_gemm(const float* __restrict__ A, const float* __restrict__ B,
       float* __restrict__ C, __half* __restrict__ Ch, int M) {
    __shared__ float As[2][8][128 + 4];
    __shared__ float Bs[2][8][128 + 4];
    int bm = blockIdx.y * 128, bn = blockIdx.x * 128;
    int tid = threadIdx.x;        // 256 threads
    int lrow = tid >> 1;          // 0..127
    int lk = (tid & 1) * 4;       // 0 or 4
    int tr = tid >> 4;            // 0..15
    int tc = tid & 15;            // 0..15

    int ar = bm + lrow;
    bool inM = (ar < M);
    const float4* Aptr = (const float4*)&A[(size_t)(inM ? ar : 0) * DD + lk];
    const float4* Bptr = (const float4*)&B[(size_t)(bn + lrow) * DD + lk];

    // prologue: tile 0 -> buffer 0
    {
        float4 av = inM ? Aptr[0] : make_float4(0.f, 0.f, 0.f, 0.f);
        float4 bv = Bptr[0];
        As[0][lk + 0][lrow] = av.x; As[0][lk + 1][lrow] = av.y;
        As[0][lk + 2][lrow] = av.z; As[0][lk + 3][lrow] = av.w;
        Bs[0][lk + 0][lrow] = bv.x; Bs[0][lk + 1][lrow] = bv.y;
        Bs[0][lk + 2][lrow] = bv.z; Bs[0][lk + 3][lrow] = bv.w;
    }
    __syncthreads();

    float acc[8][8] = {};
    #pragma unroll
    for (int t = 0; t < 32; t++) {
        int cur = t & 1;
        float4 avn, bvn;
        if (t < 31) {
            avn = inM ? Aptr[(t + 1) * 2] : make_float4(0.f, 0.f, 0.f, 0.f);
            bvn = Bptr[(t + 1) * 2];
        }
        #pragma unroll
        for (int k = 0; k < 8; k++) {
            float4 a0 = *(const float4*)&As[cur][k][tr * 4];
            float4 a1 = *(const float4*)&As[cur][k][64 + tr * 4];
            float4 b0 = *(const float4*)&Bs[cur][k][tc * 4];
            float4 b1 = *(const float4*)&Bs[cur][k][64 + tc * 4];
            float a[8] = {a0.x, a0.y, a0.z, a0.w, a1.x, a1.y, a1.z, a1.w};
            float b[8] = {b0.x, b0.y, b0.z, b0.w, b1.x, b1.y, b1.z, b1.w};
            #pragma unroll
            for (int i = 0; i < 8; i++)
                #pragma unroll
                for (int j = 0; j < 8; j++)
                    acc[i][j] = fmaf(a[i], b[j], acc[i][j]);
        }
        if (t < 31) {
            int nxt = cur ^ 1;
            As[nxt][lk + 0][lrow] = avn.x; As[nxt][lk + 1][lrow] = avn.y;
            As[nxt][lk + 2][lrow] = avn.z; As[nxt][lk + 3][lrow] = avn.w;
            Bs[nxt][lk + 0][lrow] = bvn.x; Bs[nxt][lk + 1][lrow] = bvn.y;
            Bs[nxt][lk + 2][lrow] = bvn.z; Bs[nxt][lk + 3][lrow] = bvn.w;
            __syncthreads();
        }
    }

    #pragma unroll
    for (int i = 0; i < 8; i++) {
        int r = bm + ((i < 4) ? (tr * 4 + i) : (64 + tr * 4 + i - 4));
        if (r >= M) continue;
        if (Ch) {
            __half2 h0 = __floats2half2_rn(acc[i][0], acc[i][1]);
            __half2 h1 = __floats2half2_rn(acc[i][2], acc[i][3]);
            __half2 h2 = __floats2half2_rn(acc[i][4], acc[i][5]);
            __half2 h3 = __floats2half2_rn(acc[i][6], acc[i][7]);
            uint2 pack0, pack1;
            pack0.x = *(unsigned*)&h0;
            pack0.y = *(unsigned*)&h1;
            pack1.x = *(unsigned*)&h2;
            pack1.y = *(unsigned*)&h3;
            *(uint2*)&Ch[(size_t)r * DD + bn + tc * 4]      = pack0;
            *(uint2*)&Ch[(size_t)r * DD + bn + 64 + tc * 4] = pack1;
        } else {
            float4 v0 = make_float4(acc[i][0], acc[i][1], acc[i][2], acc[i][3]);
            float4 v1 = make_float4(acc[i][4], acc[i][5], acc[i][6], acc[i][7]);
            *(float4*)&C[(size_t)r * DD + bn + tc * 4] = v0;
            *(float4*)&C[(size_t)r * DD + bn + 64 + tc * 4] = v1;
        }
    }
}

// ---------------- edge MLP: fused scores -> exp -> segment sum ----------------
__global__ void k_edge_mlp(const float* __restrict__ ea_g,
                           const float* __restrict__ w1, const float* __restrict__ b1,
                           const float* __restrict__ w2, const float* __restrict__ b2,
                           const void* __restrict__ ei) {
    __shared__ float w1p[256 * 8];   // [w1 row (6), b1, pad]
    __shared__ float w2s[256 * 16];  // w2s[j*16+t] = w2[t*256+j]
    __shared__ float b2s[16];

    int tid = threadIdx.x;           // 256 threads
    for (int idx = tid; idx < 256 * 8; idx += 256) {
        int j = idx >> 3, c = idx & 7;
        float v = 0.0f;
        if (c < 6)       v = w1[j * 6 + c];
        else if (c == 6) v = b1[j];
        w1p[idx] = v;
    }
    for (int idx = tid; idx < 256 * 16; idx += 256) {
        int j = idx >> 4, t = idx & 15;
        w2s[idx] = w2[t * 256 + j];
    }
    if (tid < 16) b2s[tid] = b2[tid];
    __syncthreads();

    int e = blockIdx.x * 256 + tid;
    if (e >= EE) return;
    int is64 = g_is64;

    float ea[6];
    #pragma unroll
    for (int k = 0; k < 6; k++) ea[k] = ea_g[(long long)e * 6 + k];

    float acc[16];
    #pragma unroll
    for (int t = 0; t < 16; t++) acc[t] = b2s[t];

    const float4* w1p4 = (const float4*)w1p;
    const float4* w2s4 = (const float4*)w2s;
    #pragma unroll 4
    for (int j = 0; j < 256; j++) {
        float4 p0 = w1p4[j * 2 + 0];
        float4 p1 = w1p4[j * 2 + 1];
        float s = p1.z;  // b1[j]
        s = fmaf(ea[0], p0.x, s); s = fmaf(ea[1], p0.y, s);
        s = fmaf(ea[2], p0.z, s); s = fmaf(ea[3], p0.w, s);
        s = fmaf(ea[4], p1.x, s); s = fmaf(ea[5], p1.y, s);
        float h = gelu_f(s);
        float4 q0 = w2s4[j * 4 + 0], q1 = w2s4[j * 4 + 1];
        float4 q2 = w2s4[j * 4 + 2], q3 = w2s4[j * 4 + 3];
        acc[0]  = fmaf(h, q0.x, acc[0]);  acc[1]  = fmaf(h, q0.y, acc[1]);
        acc[2]  = fmaf(h, q0.z, acc[2]);  acc[3]  = fmaf(h, q0.w, acc[3]);
        acc[4]  = fmaf(h, q1.x, acc[4]);  acc[5]  = fmaf(h, q1.y, acc[5]);
        acc[6]  = fmaf(h, q1.z, acc[6]);  acc[7]  = fmaf(h, q1.w, acc[7]);
        acc[8]  = fmaf(h, q2.x, acc[8]);  acc[9]  = fmaf(h, q2.y, acc[9]);
        acc[10] = fmaf(h, q2.z, acc[10]); acc[11] = fmaf(h, q2.w, acc[11]);
        acc[12] = fmaf(h, q3.x, acc[12]); acc[13] = fmaf(h, q3.y, acc[13]);
        acc[14] = fmaf(h, q3.z, acc[14]); acc[15] = fmaf(h, q3.w, acc[15]);
    }

    float ex[16];
    #pragma unroll
    for (int t = 0; t < 16; t++) ex[t] = __expf(acc[t]);

    float4* sc = (float4*)&g_exp[(long long)e * 16];
    sc[0] = make_float4(ex[0],  ex[1],  ex[2],  ex[3]);
    sc[1] = make_float4(ex[4],  ex[5],  ex[6],  ex[7]);
    sc[2] = make_float4(ex[8],  ex[9],  ex[10], ex[11]);
    sc[3] = make_float4(ex[12], ex[13], ex[14], ex[15]);

    int tgt = ldidx(ei, (long long)EE + e, is64);
    float* sbase = &g_sums[tgt * 16];
    red_add_v4(sbase + 0,  make_float4(ex[0],  ex[1],  ex[2],  ex[3]));
    red_add_v4(sbase + 4,  make_float4(ex[4],  ex[5],  ex[6],  ex[7]));
    red_add_v4(sbase + 8,  make_float4(ex[8],  ex[9],  ex[10], ex[11]));
    red_add_v4(sbase + 12, make_float4(ex[12], ex[13], ex[14], ex[15]));
}

// ---------------- finalize attn + gather V[src] (fp16) + scatter-add ----------------
// one warp per edge; lane l covers output floats [8l, 8l+8) -> head = l/4
__global__ void k_scatter(const void* __restrict__ ei, float* __restrict__ attn_out) {
    int gw = (blockIdx.x * blockDim.x + threadIdx.x) >> 5;
    if (gw >= EE) return;
    int lane = threadIdx.x & 31;
    int e = gw;
    int is64 = g_is64;
    int src = ldidx(ei, e, is64);
    int tgt = ldidx(ei, (long long)EE + e, is64);

    int h = lane >> 2;
    float e1 = g_exp[(long long)e * 16 + 2 * h];
    float e2 = g_exp[(long long)e * 16 + 2 * h + 1];
    float s1 = g_sums[tgt * 16 + 2 * h];
    float s2 = g_sums[tgt * 16 + 2 * h + 1];
    float beta = g_beta;
    float attn = e1 / s1 - beta * (e2 / s2);

    if (attn_out && (lane & 3) == 0)
        attn_out[(long long)e * HH + h] = attn;

    // 8 halves = 16B per lane
    uint4 pv = *(const uint4*)&g_Vh[(size_t)src * DD + lane * 8];
    __half2 h0 = *(__half2*)&pv.x;
    __half2 h1 = *(__half2*)&pv.y;
    __half2 h2 = *(__half2*)&pv.z;
    __half2 h3 = *(__half2*)&pv.w;
    float2 f0 = __half22float2(h0), f1 = __half22float2(h1);
    float2 f2 = __half22float2(h2), f3 = __half22float2(h3);
    float4 a = make_float4(f0.x * attn, f0.y * attn, f1.x * attn, f1.y * attn);
    float4 b = make_float4(f2.x * attn, f2.y * attn, f3.x * attn, f3.y * attn);
    float* dst = &g_acc[(size_t)tgt * DD + lane * 8];
    red_add_v4(dst, a);
    red_add_v4(dst + 4, b);
}

// ---------------- launch ----------------
extern "C" void kernel_launch(void* const* d_in, const int* in_sizes, int n_in,
                              void* d_out, int out_size) {
    const float* x    = (const float*)d_in[0];
    const float* eatt = (const float*)d_in[1];
    const float* v_w  = (const float*)d_in[2];
    const float* o_w  = (const float*)d_in[3];
    const float* e_w1 = (const float*)d_in[4];
    const float* e_b1 = (const float*)d_in[5];
    const float* e_w2 = (const float*)d_in[6];
    const float* e_b2 = (const float*)d_in[7];
    const float* lq   = (const float*)d_in[8];
    const float* lk   = (const float*)d_in[9];
    const void*  ei   = d_in[10];

    float* out = (float*)d_out;
    float* attn_out = (out_size >= ND + EH)     ? out + ND      : nullptr;
    float* beta_out = (out_size >= ND + EH + 1) ? out + ND + EH : nullptr;

    __half* gVh;
    float* gAcc;
    cudaGetSymbolAddress((void**)&gVh, g_Vh);
    cudaGetSymbolAddress((void**)&gAcc, g_acc);

    k_detect<<<1, 256>>>(ei);
    k_init<<<2048, 256>>>();
    k_beta<<<1, 128>>>(lq, lk, beta_out);

    dim3 ggrid(DD / 128, (NN + 127) / 128);
    k_gemm<<<ggrid, 256>>>(x, v_w, nullptr, gVh, NN);

    k_edge_mlp<<<EE / 256, 256>>>(eatt, e_w1, e_b1, e_w2, e_b2, ei);
    k_scatter<<<EE * 32 / 256, 256>>>(ei, attn_out);

    k_gemm<<<ggrid, 256>>>(gAcc, o_w, out, nullptr, NN);
}

// round 6
// speedup vs baseline: 2.5891x; 1.2574x over previous
#include <cuda_runtime.h>
#include <cuda_fp16.h>
#include <math.h>

#define NN 50000
#define EE 800000
#define DD 256
#define HH 8
#define ND (NN * DD)
#define EH (EE * HH)
#define LAMBDA_INIT 0.6321205588285577f

// ---------------- scratch (static device globals; no allocation) ----------------
__device__ __half g_Vh[ND];        // V = x @ v_w^T (fp16)   25.6 MB
__device__ float  g_exp[EE * 16];  // exp(scores)            51.2 MB
__device__ float  g_sums[NN * 16]; // [node][2h+j] segment sums
__device__ float  g_acc[ND];       // scatter accumulator    51.2 MB
__device__ float  g_beta;
__device__ int    g_is64;

// ---------------- helpers ----------------
__device__ __forceinline__ int ldidx(const void* p, long long i, int is64) {
    return is64 ? (int)((const long long*)p)[i] : ((const int*)p)[i];
}
__device__ __forceinline__ void red_add_v4(float* addr, float4 v) {
    asm volatile("red.global.add.v4.f32 [%0], {%1,%2,%3,%4};"
                 :: "l"(addr), "f"(v.x), "f"(v.y), "f"(v.z), "f"(v.w) : "memory");
}
__device__ __forceinline__ unsigned f2tf32(float x) {
    unsigned r;
    asm("cvt.rna.tf32.f32 %0, %1;" : "=r"(r) : "f"(x));
    return r;
}
__device__ __forceinline__ void mma_tf32(float4& c,
                                         unsigned a0, unsigned a1, unsigned a2, unsigned a3,
                                         unsigned b0, unsigned b1) {
    asm volatile("mma.sync.aligned.m16n8k8.row.col.f32.tf32.tf32.f32 "
                 "{%0,%1,%2,%3}, {%4,%5,%6,%7}, {%8,%9}, {%0,%1,%2,%3};"
                 : "+f"(c.x), "+f"(c.y), "+f"(c.z), "+f"(c.w)
                 : "r"(a0), "r"(a1), "r"(a2), "r"(a3), "r"(b0), "r"(b1));
}

// exact-enough GELU: s * Phi(s), Phi via Abramowitz-Stegun 7.1.26 erf (abs err 1.5e-7)
__device__ __forceinline__ float gelu_f(float s) {
    float x  = s * 0.70710678118654752f;
    float ax = fabsf(x);
    float t  = __fdividef(1.0f, fmaf(0.3275911f, ax, 1.0f));
    float p  = fmaf(1.061405429f, t, -1.453152027f);
    p = fmaf(p, t, 1.421413741f);
    p = fmaf(p, t, -0.284496736f);
    p = fmaf(p, t, 0.254829592f);
    p *= t;
    float e = __expf(-x * x);
    float erfax = fmaf(-p, e, 1.0f);
    float erfx  = copysignf(erfax, x);
    return s * 0.5f * (1.0f + erfx);
}

// ---------------- dtype sniff for edge_index (int32 vs int64) ----------------
__global__ void k_detect(const void* ei) {
    const int* p = (const int*)ei;
    int nz = (p[2 * threadIdx.x + 1] != 0);
    int any = __syncthreads_or(nz);
    if (threadIdx.x == 0) g_is64 = !any;
}

// ---------------- zero init (every launch; graph replays) ----------------
__global__ void k_init() {
    long long stride = (long long)gridDim.x * blockDim.x;
    for (long long i = blockIdx.x * (long long)blockDim.x + threadIdx.x; i < ND; i += stride)
        g_acc[i] = 0.0f;
    for (long long i = blockIdx.x * (long long)blockDim.x + threadIdx.x; i < NN * 16; i += stride)
        g_sums[i] = 0.0f;
}

// ---------------- beta ----------------
__global__ void k_beta(const float* __restrict__ lq, const float* __restrict__ lk,
                       float* out_beta) {
    __shared__ float red[128];
    int t = threadIdx.x;
    float p = (t < 100) ? lq[t] * lk[t] : 0.0f;
    red[t] = p;
    __syncthreads();
    for (int s = 64; s > 0; s >>= 1) {
        if (t < s) red[t] += red[t + s];
        __syncthreads();
    }
    if (t == 0) {
        float lam1 = expf(red[0]);
        float b = 1.0f / (1.0f + expf(-lam1 * LAMBDA_INIT));
        g_beta = b;
        if (out_beta) *out_beta = b;
    }
}

// ---------------- tensor-core GEMM (3xTF32): C[M,256] = A[M,256] @ B[256,256]^T --------
// 128x128 block tile, 8 warps of 32x64 (2x8 m16n8k8 atoms), K staged 32 wide.
// a = a_hi + a_lo, b = b_hi + b_lo; C += ahi*bhi + ahi*blo + alo*bhi (≈ fp32 exact).
// If Ch != nullptr writes fp16, else fp32 to C.
__global__ void __launch_bounds__(256, 2)
k_gemm_tc(const float* __restrict__ A, const float* __restrict__ B,
          float* __restrict__ C, __half* __restrict__ Ch, int M) {
    __shared__ float As[128][36];
    __shared__ float Bs[128][36];

    int bm = blockIdx.y * 128, bn = blockIdx.x * 128;
    int tid = threadIdx.x;
    int w = tid >> 5;
    int lane = tid & 31;
    int gid = lane >> 2;          // 0..7
    int tig = lane & 3;           // 0..3
    int wm = (w & 3) * 32;        // warp row base in tile
    int wn = (w >> 2) * 64;       // warp col base in tile

    int lrow = tid >> 1;          // loader row 0..127
    int lcb = (tid & 1) * 16;     // loader col base {0,16}
    int arow = bm + lrow;
    bool inM = (arow < M);
    const float* Arow = &A[(size_t)(inM ? arow : 0) * DD];
    const float* Brow = &B[(size_t)(bn + lrow) * DD];

    float4 c[2][8];
    #pragma unroll
    for (int i = 0; i < 2; i++)
        #pragma unroll
        for (int j = 0; j < 8; j++)
            c[i][j] = make_float4(0.f, 0.f, 0.f, 0.f);

    #pragma unroll 1
    for (int k0 = 0; k0 < 256; k0 += 32) {
        // stage A/B K-slab into smem
        #pragma unroll
        for (int u = 0; u < 4; u++) {
            float4 av = inM ? *(const float4*)&Arow[k0 + lcb + 4 * u]
                            : make_float4(0.f, 0.f, 0.f, 0.f);
            float4 bv = *(const float4*)&Brow[k0 + lcb + 4 * u];
            *(float4*)&As[lrow][lcb + 4 * u] = av;
            *(float4*)&Bs[lrow][lcb + 4 * u] = bv;
        }
        __syncthreads();

        #pragma unroll
        for (int kk = 0; kk < 32; kk += 8) {
            // A fragments for 2 m-atoms, split hi/lo
            unsigned ahi[2][4], alo[2][4];
            #pragma unroll
            for (int i = 0; i < 2; i++) {
                int r0 = wm + i * 16 + gid;
                float a0 = As[r0][kk + tig];
                float a1 = As[r0 + 8][kk + tig];
                float a2 = As[r0][kk + tig + 4];
                float a3 = As[r0 + 8][kk + tig + 4];
                ahi[i][0] = f2tf32(a0); alo[i][0] = __float_as_uint(a0 - __uint_as_float(ahi[i][0]));
                ahi[i][1] = f2tf32(a1); alo[i][1] = __float_as_uint(a1 - __uint_as_float(ahi[i][1]));
                ahi[i][2] = f2tf32(a2); alo[i][2] = __float_as_uint(a2 - __uint_as_float(ahi[i][2]));
                ahi[i][3] = f2tf32(a3); alo[i][3] = __float_as_uint(a3 - __uint_as_float(ahi[i][3]));
            }
            #pragma unroll
            for (int j = 0; j < 8; j++) {
                int n0 = wn + j * 8 + gid;
                float b0 = Bs[n0][kk + tig];
                float b1 = Bs[n0][kk + tig + 4];
                unsigned bh0 = f2tf32(b0), bh1 = f2tf32(b1);
                unsigned bl0 = __float_as_uint(b0 - __uint_as_float(bh0));
                unsigned bl1 = __float_as_uint(b1 - __uint_as_float(bh1));
                #pragma unroll
                for (int i = 0; i < 2; i++) {
                    mma_tf32(c[i][j], ahi[i][0], ahi[i][1], ahi[i][2], ahi[i][3], bh0, bh1);
                    mma_tf32(c[i][j], ahi[i][0], ahi[i][1], ahi[i][2], ahi[i][3], bl0, bl1);
                    mma_tf32(c[i][j], alo[i][0], alo[i][1], alo[i][2], alo[i][3], bh0, bh1);
                }
            }
        }
        __syncthreads();
    }

    // epilogue
    #pragma unroll
    for (int i = 0; i < 2; i++) {
        int r0 = bm + wm + i * 16 + gid;
        int r1 = r0 + 8;
        #pragma unroll
        for (int j = 0; j < 8; j++) {
            int col = bn + wn + j * 8 + 2 * tig;
            if (Ch) {
                if (r0 < M) {
                    __half2 h = __floats2half2_rn(c[i][j].x, c[i][j].y);
                    *(__half2*)&Ch[(size_t)r0 * DD + col] = h;
                }
                if (r1 < M) {
                    __half2 h = __floats2half2_rn(c[i][j].z, c[i][j].w);
                    *(__half2*)&Ch[(size_t)r1 * DD + col] = h;
                }
            } else {
                if (r0 < M) *(float2*)&C[(size_t)r0 * DD + col] = make_float2(c[i][j].x, c[i][j].y);
                if (r1 < M) *(float2*)&C[(size_t)r1 * DD + col] = make_float2(c[i][j].z, c[i][j].w);
            }
        }
    }
}

// ---------------- edge MLP: fused scores -> exp -> segment sum ----------------
__global__ void k_edge_mlp(const float* __restrict__ ea_g,
                           const float* __restrict__ w1, const float* __restrict__ b1,
                           const float* __restrict__ w2, const float* __restrict__ b2,
                           const void* __restrict__ ei) {
    __shared__ float w1p[256 * 8];   // [w1 row (6), b1, pad]
    __shared__ float w2s[256 * 16];  // w2s[j*16+t] = w2[t*256+j]
    __shared__ float b2s[16];

    int tid = threadIdx.x;           // 256 threads
    for (int idx = tid; idx < 256 * 8; idx += 256) {
        int j = idx >> 3, c = idx & 7;
        float v = 0.0f;
        if (c < 6)       v = w1[j * 6 + c];
        else if (c == 6) v = b1[j];
        w1p[idx] = v;
    }
    for (int idx = tid; idx < 256 * 16; idx += 256) {
        int j = idx >> 4, t = idx & 15;
        w2s[idx] = w2[t * 256 + j];
    }
    if (tid < 16) b2s[tid] = b2[tid];
    __syncthreads();

    int e = blockIdx.x * 256 + tid;
    if (e >= EE) return;
    int is64 = g_is64;

    float ea[6];
    #pragma unroll
    for (int k = 0; k < 6; k++) ea[k] = ea_g[(long long)e * 6 + k];

    float acc[16];
    #pragma unroll
    for (int t = 0; t < 16; t++) acc[t] = b2s[t];

    const float4* w1p4 = (const float4*)w1p;
    const float4* w2s4 = (const float4*)w2s;
    #pragma unroll 4
    for (int j = 0; j < 256; j++) {
        float4 p0 = w1p4[j * 2 + 0];
        float4 p1 = w1p4[j * 2 + 1];
        float s = p1.z;  // b1[j]
        s = fmaf(ea[0], p0.x, s); s = fmaf(ea[1], p0.y, s);
        s = fmaf(ea[2], p0.z, s); s = fmaf(ea[3], p0.w, s);
        s = fmaf(ea[4], p1.x, s); s = fmaf(ea[5], p1.y, s);
        float h = gelu_f(s);
        float4 q0 = w2s4[j * 4 + 0], q1 = w2s4[j * 4 + 1];
        float4 q2 = w2s4[j * 4 + 2], q3 = w2s4[j * 4 + 3];
        acc[0]  = fmaf(h, q0.x, acc[0]);  acc[1]  = fmaf(h, q0.y, acc[1]);
        acc[2]  = fmaf(h, q0.z, acc[2]);  acc[3]  = fmaf(h, q0.w, acc[3]);
        acc[4]  = fmaf(h, q1.x, acc[4]);  acc[5]  = fmaf(h, q1.y, acc[5]);
        acc[6]  = fmaf(h, q1.z, acc[6]);  acc[7]  = fmaf(h, q1.w, acc[7]);
        acc[8]  = fmaf(h, q2.x, acc[8]);  acc[9]  = fmaf(h, q2.y, acc[9]);
        acc[10] = fmaf(h, q2.z, acc[10]); acc[11] = fmaf(h, q2.w, acc[11]);
        acc[12] = fmaf(h, q3.x, acc[12]); acc[13] = fmaf(h, q3.y, acc[13]);
        acc[14] = fmaf(h, q3.z, acc[14]); acc[15] = fmaf(h, q3.w, acc[15]);
    }

    float ex[16];
    #pragma unroll
    for (int t = 0; t < 16; t++) ex[t] = __expf(acc[t]);

    float4* sc = (float4*)&g_exp[(long long)e * 16];
    sc[0] = make_float4(ex[0],  ex[1],  ex[2],  ex[3]);
    sc[1] = make_float4(ex[4],  ex[5],  ex[6],  ex[7]);
    sc[2] = make_float4(ex[8],  ex[9],  ex[10], ex[11]);
    sc[3] = make_float4(ex[12], ex[13], ex[14], ex[15]);

    int tgt = ldidx(ei, (long long)EE + e, is64);
    float* sbase = &g_sums[tgt * 16];
    red_add_v4(sbase + 0,  make_float4(ex[0],  ex[1],  ex[2],  ex[3]));
    red_add_v4(sbase + 4,  make_float4(ex[4],  ex[5],  ex[6],  ex[7]));
    red_add_v4(sbase + 8,  make_float4(ex[8],  ex[9],  ex[10], ex[11]));
    red_add_v4(sbase + 12, make_float4(ex[12], ex[13], ex[14], ex[15]));
}

// ---------------- finalize attn + gather V[src] (fp16) + scatter-add ----------------
// one warp per edge; lane l covers output floats [8l, 8l+8) -> head = l/4
__global__ void k_scatter(const void* __restrict__ ei, float* __restrict__ attn_out) {
    int gw = (blockIdx.x * blockDim.x + threadIdx.x) >> 5;
    if (gw >= EE) return;
    int lane = threadIdx.x & 31;
    int e = gw;
    int is64 = g_is64;
    int src = ldidx(ei, e, is64);
    int tgt = ldidx(ei, (long long)EE + e, is64);

    int h = lane >> 2;
    float e1 = g_exp[(long long)e * 16 + 2 * h];
    float e2 = g_exp[(long long)e * 16 + 2 * h + 1];
    float s1 = g_sums[tgt * 16 + 2 * h];
    float s2 = g_sums[tgt * 16 + 2 * h + 1];
    float beta = g_beta;
    float attn = e1 / s1 - beta * (e2 / s2);

    if (attn_out && (lane & 3) == 0)
        attn_out[(long long)e * HH + h] = attn;

    // 8 halves = 16B per lane
    uint4 pv = *(const uint4*)&g_Vh[(size_t)src * DD + lane * 8];
    __half2 h0 = *(__half2*)&pv.x;
    __half2 h1 = *(__half2*)&pv.y;
    __half2 h2 = *(__half2*)&pv.z;
    __half2 h3 = *(__half2*)&pv.w;
    float2 f0 = __half22float2(h0), f1 = __half22float2(h1);
    float2 f2 = __half22float2(h2), f3 = __half22float2(h3);
    float4 a = make_float4(f0.x * attn, f0.y * attn, f1.x * attn, f1.y * attn);
    float4 b = make_float4(f2.x * attn, f2.y * attn, f3.x * attn, f3.y * attn);
    float* dst = &g_acc[(size_t)tgt * DD + lane * 8];
    red_add_v4(dst, a);
    red_add_v4(dst + 4, b);
}

// ---------------- launch ----------------
extern "C" void kernel_launch(void* const* d_in, const int* in_sizes, int n_in,
                              void* d_out, int out_size) {
    const float* x    = (const float*)d_in[0];
    const float* eatt = (const float*)d_in[1];
    const float* v_w  = (const float*)d_in[2];
    const float* o_w  = (const float*)d_in[3];
    const float* e_w1 = (const float*)d_in[4];
    const float* e_b1 = (const float*)d_in[5];
    const float* e_w2 = (const float*)d_in[6];
    const float* e_b2 = (const float*)d_in[7];
    const float* lq   = (const float*)d_in[8];
    const float* lk   = (const float*)d_in[9];
    const void*  ei   = d_in[10];

    float* out = (float*)d_out;
    float* attn_out = (out_size >= ND + EH)     ? out + ND      : nullptr;
    float* beta_out = (out_size >= ND + EH + 1) ? out + ND + EH : nullptr;

    __half* gVh;
    float* gAcc;
    cudaGetSymbolAddress((void**)&gVh, g_Vh);
    cudaGetSymbolAddress((void**)&gAcc, g_acc);

    k_detect<<<1, 256>>>(ei);
    k_init<<<2048, 256>>>();
    k_beta<<<1, 128>>>(lq, lk, beta_out);

    dim3 ggrid(DD / 128, (NN + 127) / 128);
    k_gemm_tc<<<ggrid, 256>>>(x, v_w, nullptr, gVh, NN);

    k_edge_mlp<<<EE / 256, 256>>>(eatt, e_w1, e_b1, e_w2, e_b2, ei);
    k_scatter<<<EE * 32 / 256, 256>>>(ei, attn_out);

    k_gemm_tc<<<ggrid, 256>>>(gAcc, o_w, out, nullptr, NN);
}

// round 7
// speedup vs baseline: 2.7449x; 1.0602x over previous
#include <cuda_runtime.h>
#include <cuda_fp16.h>
#include <math.h>

#define NN 50000
#define EE 800000
#define DD 256
#define HH 8
#define ND (NN * DD)
#define EH (EE * HH)
#define LAMBDA_INIT 0.6321205588285577f

// ---------------- scratch (static device globals; no allocation) ----------------
__device__ __half g_Vh[ND];        // V = x @ v_w^T (fp16)   25.6 MB
__device__ float  g_exp[EE * 16];  // exp(scores)            51.2 MB
__device__ float  g_acc[ND];       // aggregated output      51.2 MB
__device__ int    g_cnt[NN];       // per-node degree
__device__ int    g_off[NN];       // CSR offsets
__device__ int    g_cur[NN];       // fill cursors
__device__ int    g_eid[EE];       // sorted edge ids
__device__ int    g_esrc[EE];      // sorted src nodes
__device__ float  g_beta;
__device__ int    g_is64;

// ---------------- helpers ----------------
__device__ __forceinline__ int ldidx(const void* p, long long i, int is64) {
    return is64 ? (int)((const long long*)p)[i] : ((const int*)p)[i];
}
__device__ __forceinline__ unsigned f2tf32(float x) {
    unsigned r;
    asm("cvt.rna.tf32.f32 %0, %1;" : "=r"(r) : "f"(x));
    return r;
}
__device__ __forceinline__ void mma_tf32(float4& c,
                                         unsigned a0, unsigned a1, unsigned a2, unsigned a3,
                                         unsigned b0, unsigned b1) {
    asm volatile("mma.sync.aligned.m16n8k8.row.col.f32.tf32.tf32.f32 "
                 "{%0,%1,%2,%3}, {%4,%5,%6,%7}, {%8,%9}, {%0,%1,%2,%3};"
                 : "+f"(c.x), "+f"(c.y), "+f"(c.z), "+f"(c.w)
                 : "r"(a0), "r"(a1), "r"(a2), "r"(a3), "r"(b0), "r"(b1));
}

// exact-enough GELU: s * Phi(s), Phi via Abramowitz-Stegun 7.1.26 erf (abs err 1.5e-7)
__device__ __forceinline__ float gelu_f(float s) {
    float x  = s * 0.70710678118654752f;
    float ax = fabsf(x);
    float t  = __fdividef(1.0f, fmaf(0.3275911f, ax, 1.0f));
    float p  = fmaf(1.061405429f, t, -1.453152027f);
    p = fmaf(p, t, 1.421413741f);
    p = fmaf(p, t, -0.284496736f);
    p = fmaf(p, t, 0.254829592f);
    p *= t;
    float e = __expf(-x * x);
    float erfax = fmaf(-p, e, 1.0f);
    float erfx  = copysignf(erfax, x);
    return s * 0.5f * (1.0f + erfx);
}

// ---------------- dtype sniff for edge_index (int32 vs int64) ----------------
__global__ void k_detect(const void* ei) {
    const int* p = (const int*)ei;
    int nz = (p[2 * threadIdx.x + 1] != 0);
    int any = __syncthreads_or(nz);
    if (threadIdx.x == 0) g_is64 = !any;
}

// ---------------- zero degree counters (every replay) ----------------
__global__ void k_zero() {
    int i = blockIdx.x * blockDim.x + threadIdx.x;
    if (i < NN) g_cnt[i] = 0;
}

// ---------------- beta ----------------
__global__ void k_beta(const float* __restrict__ lq, const float* __restrict__ lk,
                       float* out_beta) {
    __shared__ float red[128];
    int t = threadIdx.x;
    float p = (t < 100) ? lq[t] * lk[t] : 0.0f;
    red[t] = p;
    __syncthreads();
    for (int s = 64; s > 0; s >>= 1) {
        if (t < s) red[t] += red[t + s];
        __syncthreads();
    }
    if (t == 0) {
        float lam1 = expf(red[0]);
        float b = 1.0f / (1.0f + expf(-lam1 * LAMBDA_INIT));
        g_beta = b;
        if (out_beta) *out_beta = b;
    }
}

// ---------------- CSR build: histogram ----------------
__global__ void k_hist(const void* __restrict__ ei) {
    int e = blockIdx.x * blockDim.x + threadIdx.x;
    if (e >= EE) return;
    int tgt = ldidx(ei, (long long)EE + e, g_is64);
    atomicAdd(&g_cnt[tgt], 1);
}

// ---------------- CSR build: exclusive scan (single block, 1024 thr) ----------------
__global__ void k_scan() {
    __shared__ int s[1024];
    __shared__ int carry;
    int tid = threadIdx.x;
    if (tid == 0) carry = 0;
    __syncthreads();
    for (int base = 0; base < NN; base += 1024) {
        int i = base + tid;
        int v = (i < NN) ? g_cnt[i] : 0;
        s[tid] = v;
        __syncthreads();
        #pragma unroll
        for (int d = 1; d < 1024; d <<= 1) {
            int t = (tid >= d) ? s[tid - d] : 0;
            __syncthreads();
            s[tid] += t;
            __syncthreads();
        }
        int excl = s[tid] - v + carry;
        if (i < NN) { g_off[i] = excl; g_cur[i] = excl; }
        __syncthreads();
        if (tid == 0) carry += s[1023];
        __syncthreads();
    }
}

// ---------------- CSR build: fill ----------------
__global__ void k_fill(const void* __restrict__ ei) {
    int e = blockIdx.x * blockDim.x + threadIdx.x;
    if (e >= EE) return;
    int is64 = g_is64;
    int tgt = ldidx(ei, (long long)EE + e, is64);
    int src = ldidx(ei, e, is64);
    int pos = atomicAdd(&g_cur[tgt], 1);
    g_eid[pos] = e;
    g_esrc[pos] = src;
}

// ---------------- tensor-core GEMM (3xTF32): C[M,256] = A[M,256] @ B[256,256]^T --------
__global__ void __launch_bounds__(256, 2)
k_gemm_tc(const float* __restrict__ A, const float* __restrict__ B,
          float* __restrict__ C, __half* __restrict__ Ch, int M) {
    __shared__ float As[128][36];
    __shared__ float Bs[128][36];

    int bm = blockIdx.y * 128, bn = blockIdx.x * 128;
    int tid = threadIdx.x;
    int w = tid >> 5;
    int lane = tid & 31;
    int gid = lane >> 2;          // 0..7
    int tig = lane & 3;           // 0..3
    int wm = (w & 3) * 32;        // warp row base in tile
    int wn = (w >> 2) * 64;       // warp col base in tile

    int lrow = tid >> 1;          // loader row 0..127
    int lcb = (tid & 1) * 16;     // loader col base {0,16}
    int arow = bm + lrow;
    bool inM = (arow < M);
    const float* Arow = &A[(size_t)(inM ? arow : 0) * DD];
    const float* Brow = &B[(size_t)(bn + lrow) * DD];

    float4 c[2][8];
    #pragma unroll
    for (int i = 0; i < 2; i++)
        #pragma unroll
        for (int j = 0; j < 8; j++)
            c[i][j] = make_float4(0.f, 0.f, 0.f, 0.f);

    #pragma unroll 1
    for (int k0 = 0; k0 < 256; k0 += 32) {
        #pragma unroll
        for (int u = 0; u < 4; u++) {
            float4 av = inM ? *(const float4*)&Arow[k0 + lcb + 4 * u]
                            : make_float4(0.f, 0.f, 0.f, 0.f);
            float4 bv = *(const float4*)&Brow[k0 + lcb + 4 * u];
            *(float4*)&As[lrow][lcb + 4 * u] = av;
            *(float4*)&Bs[lrow][lcb + 4 * u] = bv;
        }
        __syncthreads();

        #pragma unroll
        for (int kk = 0; kk < 32; kk += 8) {
            unsigned ahi[2][4], alo[2][4];
            #pragma unroll
            for (int i = 0; i < 2; i++) {
                int r0 = wm + i * 16 + gid;
                float a0 = As[r0][kk + tig];
                float a1 = As[r0 + 8][kk + tig];
                float a2 = As[r0][kk + tig + 4];
                float a3 = As[r0 + 8][kk + tig + 4];
                ahi[i][0] = f2tf32(a0); alo[i][0] = __float_as_uint(a0 - __uint_as_float(ahi[i][0]));
                ahi[i][1] = f2tf32(a1); alo[i][1] = __float_as_uint(a1 - __uint_as_float(ahi[i][1]));
                ahi[i][2] = f2tf32(a2); alo[i][2] = __float_as_uint(a2 - __uint_as_float(ahi[i][2]));
                ahi[i][3] = f2tf32(a3); alo[i][3] = __float_as_uint(a3 - __uint_as_float(ahi[i][3]));
            }
            #pragma unroll
            for (int j = 0; j < 8; j++) {
                int n0 = wn + j * 8 + gid;
                float b0 = Bs[n0][kk + tig];
                float b1 = Bs[n0][kk + tig + 4];
                unsigned bh0 = f2tf32(b0), bh1 = f2tf32(b1);
                unsigned bl0 = __float_as_uint(b0 - __uint_as_float(bh0));
                unsigned bl1 = __float_as_uint(b1 - __uint_as_float(bh1));
                #pragma unroll
                for (int i = 0; i < 2; i++) {
                    mma_tf32(c[i][j], ahi[i][0], ahi[i][1], ahi[i][2], ahi[i][3], bh0, bh1);
                    mma_tf32(c[i][j], ahi[i][0], ahi[i][1], ahi[i][2], ahi[i][3], bl0, bl1);
                    mma_tf32(c[i][j], alo[i][0], alo[i][1], alo[i][2], alo[i][3], bh0, bh1);
                }
            }
        }
        __syncthreads();
    }

    #pragma unroll
    for (int i = 0; i < 2; i++) {
        int r0 = bm + wm + i * 16 + gid;
        int r1 = r0 + 8;
        #pragma unroll
        for (int j = 0; j < 8; j++) {
            int col = bn + wn + j * 8 + 2 * tig;
            if (Ch) {
                if (r0 < M) {
                    __half2 h = __floats2half2_rn(c[i][j].x, c[i][j].y);
                    *(__half2*)&Ch[(size_t)r0 * DD + col] = h;
                }
                if (r1 < M) {
                    __half2 h = __floats2half2_rn(c[i][j].z, c[i][j].w);
                    *(__half2*)&Ch[(size_t)r1 * DD + col] = h;
                }
            } else {
                if (r0 < M) *(float2*)&C[(size_t)r0 * DD + col] = make_float2(c[i][j].x, c[i][j].y);
                if (r1 < M) *(float2*)&C[(size_t)r1 * DD + col] = make_float2(c[i][j].z, c[i][j].w);
            }
        }
    }
}

// ---------------- edge MLP: scores -> exp (no atomics) ----------------
__global__ void k_edge_mlp(const float* __restrict__ ea_g,
                           const float* __restrict__ w1, const float* __restrict__ b1,
                           const float* __restrict__ w2, const float* __restrict__ b2) {
    __shared__ float w1p[256 * 8];   // [w1 row (6), b1, pad]
    __shared__ float w2s[256 * 16];  // w2s[j*16+t] = w2[t*256+j]
    __shared__ float b2s[16];

    int tid = threadIdx.x;           // 256 threads
    for (int idx = tid; idx < 256 * 8; idx += 256) {
        int j = idx >> 3, c = idx & 7;
        float v = 0.0f;
        if (c < 6)       v = w1[j * 6 + c];
        else if (c == 6) v = b1[j];
        w1p[idx] = v;
    }
    for (int idx = tid; idx < 256 * 16; idx += 256) {
        int j = idx >> 4, t = idx & 15;
        w2s[idx] = w2[t * 256 + j];
    }
    if (tid < 16) b2s[tid] = b2[tid];
    __syncthreads();

    int e = blockIdx.x * 256 + tid;
    if (e >= EE) return;

    float ea[6];
    #pragma unroll
    for (int k = 0; k < 6; k++) ea[k] = ea_g[(long long)e * 6 + k];

    float acc[16];
    #pragma unroll
    for (int t = 0; t < 16; t++) acc[t] = b2s[t];

    const float4* w1p4 = (const float4*)w1p;
    const float4* w2s4 = (const float4*)w2s;
    #pragma unroll 4
    for (int j = 0; j < 256; j++) {
        float4 p0 = w1p4[j * 2 + 0];
        float4 p1 = w1p4[j * 2 + 1];
        float s = p1.z;  // b1[j]
        s = fmaf(ea[0], p0.x, s); s = fmaf(ea[1], p0.y, s);
        s = fmaf(ea[2], p0.z, s); s = fmaf(ea[3], p0.w, s);
        s = fmaf(ea[4], p1.x, s); s = fmaf(ea[5], p1.y, s);
        float h = gelu_f(s);
        float4 q0 = w2s4[j * 4 + 0], q1 = w2s4[j * 4 + 1];
        float4 q2 = w2s4[j * 4 + 2], q3 = w2s4[j * 4 + 3];
        acc[0]  = fmaf(h, q0.x, acc[0]);  acc[1]  = fmaf(h, q0.y, acc[1]);
        acc[2]  = fmaf(h, q0.z, acc[2]);  acc[3]  = fmaf(h, q0.w, acc[3]);
        acc[4]  = fmaf(h, q1.x, acc[4]);  acc[5]  = fmaf(h, q1.y, acc[5]);
        acc[6]  = fmaf(h, q1.z, acc[6]);  acc[7]  = fmaf(h, q1.w, acc[7]);
        acc[8]  = fmaf(h, q2.x, acc[8]);  acc[9]  = fmaf(h, q2.y, acc[9]);
        acc[10] = fmaf(h, q2.z, acc[10]); acc[11] = fmaf(h, q2.w, acc[11]);
        acc[12] = fmaf(h, q3.x, acc[12]); acc[13] = fmaf(h, q3.y, acc[13]);
        acc[14] = fmaf(h, q3.z, acc[14]); acc[15] = fmaf(h, q3.w, acc[15]);
    }

    float4* sc = (float4*)&g_exp[(long long)e * 16];
    sc[0] = make_float4(__expf(acc[0]),  __expf(acc[1]),  __expf(acc[2]),  __expf(acc[3]));
    sc[1] = make_float4(__expf(acc[4]),  __expf(acc[5]),  __expf(acc[6]),  __expf(acc[7]));
    sc[2] = make_float4(__expf(acc[8]),  __expf(acc[9]),  __expf(acc[10]), __expf(acc[11]));
    sc[3] = make_float4(__expf(acc[12]), __expf(acc[13]), __expf(acc[14]), __expf(acc[15]));
}

// ---------------- per-node aggregation: sums + attn + gather + plain store --------
// one warp per node; lane l covers output floats [8l, 8l+8), head = l/4
__global__ void k_agg(float* __restrict__ attn_out) {
    int n = (blockIdx.x * blockDim.x + threadIdx.x) >> 5;
    if (n >= NN) return;
    int lane = threadIdx.x & 31;
    int h = lane >> 2;

    int start = g_off[n];
    int cnt = g_cnt[n];
    float beta = g_beta;

    // pass 1: segment sums for this head (4 lanes per head redundantly; broadcast loads)
    float s1 = 0.f, s2 = 0.f;
    for (int i = 0; i < cnt; i++) {
        int eid = g_eid[start + i];
        float2 ee = *(const float2*)&g_exp[(size_t)eid * 16 + 2 * h];
        s1 += ee.x;
        s2 += ee.y;
    }
    float inv1 = (cnt > 0) ? 1.0f / s1 : 0.0f;
    float inv2 = (cnt > 0) ? 1.0f / s2 : 0.0f;

    // pass 2: attn + gather + accumulate
    float acc[8] = {0.f, 0.f, 0.f, 0.f, 0.f, 0.f, 0.f, 0.f};
    for (int i = 0; i < cnt; i++) {
        int eid = g_eid[start + i];
        int src = g_esrc[start + i];
        float2 ee = *(const float2*)&g_exp[(size_t)eid * 16 + 2 * h];
        float attn = ee.x * inv1 - beta * (ee.y * inv2);
        if (attn_out && (lane & 3) == 0)
            attn_out[(size_t)eid * HH + h] = attn;
        uint4 pv = *(const uint4*)&g_Vh[(size_t)src * DD + lane * 8];
        __half2 h0 = *(__half2*)&pv.x;
        __half2 h1 = *(__half2*)&pv.y;
        __half2 h2 = *(__half2*)&pv.z;
        __half2 h3 = *(__half2*)&pv.w;
        float2 f0 = __half22float2(h0), f1 = __half22float2(h1);
        float2 f2 = __half22float2(h2), f3 = __half22float2(h3);
        acc[0] = fmaf(attn, f0.x, acc[0]); acc[1] = fmaf(attn, f0.y, acc[1]);
        acc[2] = fmaf(attn, f1.x, acc[2]); acc[3] = fmaf(attn, f1.y, acc[3]);
        acc[4] = fmaf(attn, f2.x, acc[4]); acc[5] = fmaf(attn, f2.y, acc[5]);
        acc[6] = fmaf(attn, f3.x, acc[6]); acc[7] = fmaf(attn, f3.y, acc[7]);
    }

    float* dst = &g_acc[(size_t)n * DD + lane * 8];
    *(float4*)dst       = make_float4(acc[0], acc[1], acc[2], acc[3]);
    *(float4*)(dst + 4) = make_float4(acc[4], acc[5], acc[6], acc[7]);
}

// ---------------- launch ----------------
extern "C" void kernel_launch(void* const* d_in, const int* in_sizes, int n_in,
                              void* d_out, int out_size) {
    const float* x    = (const float*)d_in[0];
    const float* eatt = (const float*)d_in[1];
    const float* v_w  = (const float*)d_in[2];
    const float* o_w  = (const float*)d_in[3];
    const float* e_w1 = (const float*)d_in[4];
    const float* e_b1 = (const float*)d_in[5];
    const float* e_w2 = (const float*)d_in[6];
    const float* e_b2 = (const float*)d_in[7];
    const float* lq   = (const float*)d_in[8];
    const float* lk   = (const float*)d_in[9];
    const void*  ei   = d_in[10];

    float* out = (float*)d_out;
    float* attn_out = (out_size >= ND + EH)     ? out + ND      : nullptr;
    float* beta_out = (out_size >= ND + EH + 1) ? out + ND + EH : nullptr;

    __half* gVh;
    float* gAcc;
    cudaGetSymbolAddress((void**)&gVh, g_Vh);
    cudaGetSymbolAddress((void**)&gAcc, g_acc);

    k_detect<<<1, 256>>>(ei);
    k_zero<<<(NN + 255) / 256, 256>>>();
    k_beta<<<1, 128>>>(lq, lk, beta_out);
    k_hist<<<EE / 256, 256>>>(ei);

    dim3 ggrid(DD / 128, (NN + 127) / 128);
    k_gemm_tc<<<ggrid, 256>>>(x, v_w, nullptr, gVh, NN);

    k_edge_mlp<<<EE / 256, 256>>>(eatt, e_w1, e_b1, e_w2, e_b2);

    k_scan<<<1, 1024>>>();
    k_fill<<<EE / 256, 256>>>(ei);
    k_agg<<<(NN * 32 + 255) / 256, 256>>>(attn_out);

    k_gemm_tc<<<ggrid, 256>>>(gAcc, o_w, out, nullptr, NN);
}